// round 6
// baseline (speedup 1.0000x reference)
#include <cuda_runtime.h>
#include <math.h>
#include <stddef.h>

// ---------------- problem constants ----------------
#define SQv   2048
#define Dv    1024
#define Hv    16
#define DHv   64
#define NCv   4096
#define LTv   16      // tables
#define KHv   8       // hash funcs per table
#define LKv   128     // LT*KH
#define NBv   256     // buckets
#define TPPv  1024
#define SSv   1024    // sample budget
#define PPv   64
#define NTOK  2048    // total tokens (2 chunks)

// ---------------- device scratch ----------------
__device__ __align__(16) float g_xln   [SQv*Dv];
__device__ __align__(16) float g_q     [SQv*Dv];
__device__ __align__(16) float g_k     [SQv*Dv];
__device__ __align__(16) float g_v     [SQv*Dv];
__device__ __align__(16) float g_ctx   [SQv*Dv];
__device__ __align__(16) float g_attn  [SQv*Dv];
__device__ __align__(16) float g_normed[SQv*Dv];
__device__ __align__(16) float g_projn [LKv*NCv];
__device__ __align__(16) float g_projt [LKv*NTOK];
__device__ __align__(16) float g_tanhpt[NTOK*LKv];
__device__ __align__(16) float g_tanhpns[2*SSv*LKv];
__device__ __align__(16) float g_w1s   [2*SSv*Dv];
__device__ __align__(16) float g_w2sT  [2*Dv*SSv];
__device__ __align__(16) float g_b1s   [2*SSv];
__device__ __align__(16) float g_logits[NTOK*SSv];
__device__ __align__(16) float g_acts  [NTOK*SSv];
__device__ __align__(16) float g_trip  [NTOK];
__device__ int g_coden[LTv*NCv];
__device__ int g_hist [2*LTv*NBv];
__device__ int g_score[2*NCv];
__device__ int g_sids [2*SSv];

// ---------------- helpers ----------------
__device__ __forceinline__ unsigned f2tf(float x){
    unsigned u; asm("cvt.rna.tf32.f32 %0, %1;" : "=r"(u) : "f"(x)); return u;
}
__device__ __forceinline__ void mma8(float* d, const unsigned* a, const unsigned* b){
    asm volatile("mma.sync.aligned.m16n8k8.row.col.f32.tf32.tf32.f32 "
        "{%0,%1,%2,%3},{%4,%5,%6,%7},{%8,%9},{%0,%1,%2,%3};"
        : "+f"(d[0]), "+f"(d[1]), "+f"(d[2]), "+f"(d[3])
        : "r"(a[0]), "r"(a[1]), "r"(a[2]), "r"(a[3]), "r"(b[0]), "r"(b[1]));
}
__device__ __forceinline__ float gelu_exact(float x){
    return 0.5f * x * (1.f + erff(x * 0.70710678118654752f));
}

struct P3 { const float* a; const float* b; const float* c; };
struct O3 { float* a; float* b; float* c; };
__device__ __forceinline__ const float* sel3(P3 p, int z){ return z==0?p.a:(z==1?p.b:p.c); }
__device__ __forceinline__ float* sel3o(O3 p, int z){ return z==0?p.a:(z==1?p.b:p.c); }

// ---------------- LayerNorm ----------------
__global__ void ln_kernel(const float* __restrict__ x, const float* __restrict__ g,
                          const float* __restrict__ b, float* __restrict__ y)
{
    int row = blockIdx.x;
    const float* xr = x + (size_t)row * Dv;
    __shared__ float red[256];
    int tid = threadIdx.x;
    float s = 0.f, ss = 0.f;
    for (int i = tid; i < Dv; i += 256) { float v = xr[i]; s += v; ss += v * v; }
    red[tid] = s; __syncthreads();
    for (int st = 128; st > 0; st >>= 1) { if (tid < st) red[tid] += red[tid + st]; __syncthreads(); }
    float mean = red[0] / Dv;
    __syncthreads();
    red[tid] = ss; __syncthreads();
    for (int st = 128; st > 0; st >>= 1) { if (tid < st) red[tid] += red[tid + st]; __syncthreads(); }
    float var = red[0] / Dv - mean * mean;
    float inv = rsqrtf(var + 1e-12f);
    float* yr = y + (size_t)row * Dv;
    for (int i = tid; i < Dv; i += 256) yr[i] = (xr[i] - mean) * inv * g[i] + b[i];
}

// ---------------- TF32 tensor-core GEMM NT (grid.z multiplexed) ----------------
// C[M,N] = A[M,K]*B[N,K]^T ; SPLIT=3 -> 3xTF32, SPLIT=1 -> plain TF32.
// z-dim: A += z*zA; B = sel3(B,z)+z*zB; bias = sel3(bias,z)+z*zBias;
//        res += z*zRes; C = sel3o(C,z)+z*zC; C2 += z*zC2.
template<int SPLIT, int EPI, bool BIAS, bool RES, int BM_, int BN_>
__global__ void __launch_bounds__(256, 1)
mma_nt(const float* __restrict__ A, P3 Bp3, P3 bias3, const float* __restrict__ res,
       O3 C3, float* __restrict__ C2,
       long zA, long zB, long zBias, long zRes, long zC, long zC2,
       int M, int N, int K)
{
    constexpr int BK = 32, LD = 36;
    constexpr int WTM = BM_ / 2, WTN = BN_ / 4;
    constexpr int MT = WTM / 16, NT = WTN / 8;
    extern __shared__ unsigned sm[];
    unsigned* Ah = sm;
    unsigned* Bh = Ah + BM_ * LD;
    unsigned* Al = (SPLIT == 3) ? Bh + BN_ * LD : Ah;
    unsigned* Bl = (SPLIT == 3) ? Al + BM_ * LD : Bh;

    const int z = blockIdx.z;
    A += (size_t)z * zA;
    const float* B = sel3(Bp3, z) + (size_t)z * zB;
    const float* bias = sel3(bias3, z) + (size_t)z * zBias;
    if (RES) res += (size_t)z * zRes;
    float* C = sel3o(C3, z) + (size_t)z * zC;
    if (EPI == 1) C2 += (size_t)z * zC2;

    const int tid = threadIdx.x;
    const int lane = tid & 31, wid = tid >> 5;
    const int wm = wid & 1, wn = wid >> 1;
    const int m0 = blockIdx.y * BM_, n0 = blockIdx.x * BN_;

    constexpr int PA = BM_ / 32;
    constexpr int PB = BN_ / 32;
    const int lrw = tid >> 3;
    const int lcc = (tid & 7) * 4;

    float4 pa[PA], pb[PB];
    float acc[MT][NT][4];
    #pragma unroll
    for (int i = 0; i < MT; i++)
        #pragma unroll
        for (int j = 0; j < NT; j++)
            #pragma unroll
            for (int u = 0; u < 4; u++) acc[i][j][u] = 0.f;

    #pragma unroll
    for (int p = 0; p < PA; p++)
        pa[p] = *(const float4*)(A + (size_t)(m0 + p*32 + lrw) * K + lcc);
    #pragma unroll
    for (int p = 0; p < PB; p++)
        pb[p] = *(const float4*)(B + (size_t)(n0 + p*32 + lrw) * K + lcc);

    const int ntiles = K / BK;
    for (int kt = 0; kt < ntiles; kt++) {
        __syncthreads();
        #pragma unroll
        for (int p = 0; p < PA; p++) {
            float vv[4] = {pa[p].x, pa[p].y, pa[p].z, pa[p].w};
            #pragma unroll
            for (int i = 0; i < 4; i++) {
                unsigned h = f2tf(vv[i]);
                Ah[(p*32 + lrw) * LD + lcc + i] = h;
                if (SPLIT == 3)
                    Al[(p*32 + lrw) * LD + lcc + i] = f2tf(vv[i] - __uint_as_float(h));
            }
        }
        #pragma unroll
        for (int p = 0; p < PB; p++) {
            float vv[4] = {pb[p].x, pb[p].y, pb[p].z, pb[p].w};
            #pragma unroll
            for (int i = 0; i < 4; i++) {
                unsigned h = f2tf(vv[i]);
                Bh[(p*32 + lrw) * LD + lcc + i] = h;
                if (SPLIT == 3)
                    Bl[(p*32 + lrw) * LD + lcc + i] = f2tf(vv[i] - __uint_as_float(h));
            }
        }
        __syncthreads();
        if (kt + 1 < ntiles) {
            const float* An = A + (size_t)(kt + 1) * BK;
            const float* Bn = B + (size_t)(kt + 1) * BK;
            #pragma unroll
            for (int p = 0; p < PA; p++)
                pa[p] = *(const float4*)(An + (size_t)(m0 + p*32 + lrw) * K + lcc);
            #pragma unroll
            for (int p = 0; p < PB; p++)
                pb[p] = *(const float4*)(Bn + (size_t)(n0 + p*32 + lrw) * K + lcc);
        }
        #pragma unroll
        for (int ks = 0; ks < 4; ks++) {
            unsigned ah[MT][4], al[MT][4], bh[NT][2], bl[NT][2];
            #pragma unroll
            for (int i = 0; i < MT; i++) {
                int r = wm * WTM + i * 16 + (lane >> 2);
                int c = ks * 8 + (lane & 3);
                ah[i][0] = Ah[r*LD + c];       ah[i][1] = Ah[(r+8)*LD + c];
                ah[i][2] = Ah[r*LD + c + 4];   ah[i][3] = Ah[(r+8)*LD + c + 4];
                if (SPLIT == 3) {
                    al[i][0] = Al[r*LD + c];     al[i][1] = Al[(r+8)*LD + c];
                    al[i][2] = Al[r*LD + c + 4]; al[i][3] = Al[(r+8)*LD + c + 4];
                }
            }
            #pragma unroll
            for (int j = 0; j < NT; j++) {
                int r = wn * WTN + j * 8 + (lane >> 2);
                int c = ks * 8 + (lane & 3);
                bh[j][0] = Bh[r*LD + c];  bh[j][1] = Bh[r*LD + c + 4];
                if (SPLIT == 3) {
                    bl[j][0] = Bl[r*LD + c];  bl[j][1] = Bl[r*LD + c + 4];
                }
            }
            #pragma unroll
            for (int i = 0; i < MT; i++)
                #pragma unroll
                for (int j = 0; j < NT; j++) {
                    mma8(acc[i][j], ah[i], bh[j]);
                    if (SPLIT == 3) {
                        mma8(acc[i][j], ah[i], bl[j]);
                        mma8(acc[i][j], al[i], bh[j]);
                    }
                }
        }
    }
    #pragma unroll
    for (int i = 0; i < MT; i++) {
        #pragma unroll
        for (int j = 0; j < NT; j++) {
            int r = m0 + wm * WTM + i * 16 + (lane >> 2);
            int c = n0 + wn * WTN + j * 8 + (lane & 3) * 2;
            float v00 = acc[i][j][0], v01 = acc[i][j][1];
            float v10 = acc[i][j][2], v11 = acc[i][j][3];
            if (BIAS) { float b0 = bias[c], b1 = bias[c+1]; v00 += b0; v01 += b1; v10 += b0; v11 += b1; }
            if (RES) {
                v00 += res[(size_t)r*N + c];     v01 += res[(size_t)r*N + c + 1];
                v10 += res[(size_t)(r+8)*N + c]; v11 += res[(size_t)(r+8)*N + c + 1];
            }
            *(float2*)(C + (size_t)r*N + c)     = make_float2(v00, v01);
            *(float2*)(C + (size_t)(r+8)*N + c) = make_float2(v10, v11);
            if (EPI == 1) {
                *(float2*)(C2 + (size_t)r*N + c)     = make_float2(gelu_exact(v00), gelu_exact(v01));
                *(float2*)(C2 + (size_t)(r+8)*N + c) = make_float2(gelu_exact(v10), gelu_exact(v11));
            }
        }
    }
}

// ---------------- exact-fp32 GEMM NT (hash projections only) ----------------
template<bool HAS_BIAS>
__global__ void gemm_nt(const float* __restrict__ A, const float* __restrict__ Bm,
                        const float* __restrict__ bias,
                        float* __restrict__ C, int M, int N, int Kd)
{
    __shared__ float As[16][64];
    __shared__ float Bs[16][64];
    int tid = threadIdx.x;
    int tx = tid & 15, ty = tid >> 4;
    int m0 = blockIdx.y * 64, n0 = blockIdx.x * 64;
    float acc[4][4] = {};
    for (int k0 = 0; k0 < Kd; k0 += 16) {
        int idx = tid * 4;
        int r = idx >> 4, kk = idx & 15;
        float4 av = *(const float4*)(A  + (size_t)(m0 + r) * Kd + k0 + kk);
        As[kk+0][r] = av.x; As[kk+1][r] = av.y; As[kk+2][r] = av.z; As[kk+3][r] = av.w;
        float4 bv = *(const float4*)(Bm + (size_t)(n0 + r) * Kd + k0 + kk);
        Bs[kk+0][r] = bv.x; Bs[kk+1][r] = bv.y; Bs[kk+2][r] = bv.z; Bs[kk+3][r] = bv.w;
        __syncthreads();
        #pragma unroll
        for (int q = 0; q < 16; q++) {
            float a[4], b[4];
            #pragma unroll
            for (int i = 0; i < 4; i++) a[i] = As[q][ty*4+i];
            #pragma unroll
            for (int j = 0; j < 4; j++) b[j] = Bs[q][tx*4+j];
            #pragma unroll
            for (int i = 0; i < 4; i++)
                #pragma unroll
                for (int j = 0; j < 4; j++)
                    acc[i][j] += a[i] * b[j];
        }
        __syncthreads();
    }
    #pragma unroll
    for (int i = 0; i < 4; i++) {
        int m = m0 + ty*4 + i;
        #pragma unroll
        for (int j = 0; j < 4; j++) {
            int n = n0 + tx*4 + j;
            float v = acc[i][j];
            if (HAS_BIAS) v += bias[n];
            C[(size_t)m * N + n] = v;
        }
    }
}

// ---------------- attention: 3xTF32 tensor-core flash ----------------
#define LDQ 68
#define LDVt 72
__global__ void __launch_bounds__(128, 2)
attn3(const float* __restrict__ q, const float* __restrict__ k,
      const float* __restrict__ v, const float* __restrict__ mask,
      float* __restrict__ ctx)
{
    extern __shared__ unsigned sm[];
    unsigned* QPh = sm;
    unsigned* QPl = QPh + 64*LDQ;
    unsigned* Kh  = QPl + 64*LDQ;
    unsigned* Kl  = Kh  + 64*LDQ;
    unsigned* Vh  = Kl  + 64*LDQ;
    unsigned* Vl  = Vh  + 64*LDVt;
    float*    Ms  = (float*)(Vl + 64*LDVt);

    const int tid = threadIdx.x;
    const int lane = tid & 31, w = tid >> 5;
    const int h = blockIdx.y, q0 = blockIdx.x * 64;
    const int rr = w * 16 + (lane >> 2);

    for (int idx = tid; idx < 64 * 16; idx += 128) {
        int row = idx >> 4, c4 = (idx & 15) * 4;
        float4 t = *(const float4*)(q + (size_t)(q0 + row) * Dv + h * 64 + c4);
        float vv[4] = {t.x, t.y, t.z, t.w};
        #pragma unroll
        for (int u = 0; u < 4; u++) {
            unsigned hi = f2tf(vv[u]);
            QPh[row * LDQ + c4 + u] = hi;
            QPl[row * LDQ + c4 + u] = f2tf(vv[u] - __uint_as_float(hi));
        }
    }
    __syncthreads();

    unsigned qh[8][4], ql[8][4];
    #pragma unroll
    for (int ks = 0; ks < 8; ks++) {
        int c = ks * 8 + (lane & 3);
        qh[ks][0] = QPh[rr*LDQ + c];       qh[ks][1] = QPh[(rr+8)*LDQ + c];
        qh[ks][2] = QPh[rr*LDQ + c + 4];   qh[ks][3] = QPh[(rr+8)*LDQ + c + 4];
        ql[ks][0] = QPl[rr*LDQ + c];       ql[ks][1] = QPl[(rr+8)*LDQ + c];
        ql[ks][2] = QPl[rr*LDQ + c + 4];   ql[ks][3] = QPl[(rr+8)*LDQ + c + 4];
    }

    float o[8][4];
    #pragma unroll
    for (int j = 0; j < 8; j++)
        #pragma unroll
        for (int u = 0; u < 4; u++) o[j][u] = 0.f;
    float m0r = -1e30f, m1r = -1e30f, l0 = 0.f, l1 = 0.f;

    for (int kt = 0; kt < SQv / 64; kt++) {
        int k0 = kt * 64;
        __syncthreads();
        for (int idx = tid; idx < 64 * 16; idx += 128) {
            int row = idx >> 4, c4 = (idx & 15) * 4;
            float4 tk = *(const float4*)(k + (size_t)(k0 + row) * Dv + h * 64 + c4);
            float kv[4] = {tk.x, tk.y, tk.z, tk.w};
            #pragma unroll
            for (int u = 0; u < 4; u++) {
                unsigned hi = f2tf(kv[u]);
                Kh[row * LDQ + c4 + u] = hi;
                Kl[row * LDQ + c4 + u] = f2tf(kv[u] - __uint_as_float(hi));
            }
            float4 tv = *(const float4*)(v + (size_t)(k0 + row) * Dv + h * 64 + c4);
            float vv[4] = {tv.x, tv.y, tv.z, tv.w};
            #pragma unroll
            for (int u = 0; u < 4; u++) {
                unsigned hi = f2tf(vv[u]);
                Vh[row * LDVt + c4 + u] = hi;
                Vl[row * LDVt + c4 + u] = f2tf(vv[u] - __uint_as_float(hi));
            }
        }
        if (tid < 64) Ms[tid] = -1000.f * (1.f - mask[k0 + tid]);
        __syncthreads();

        float s[8][4];
        #pragma unroll
        for (int j = 0; j < 8; j++)
            #pragma unroll
            for (int u = 0; u < 4; u++) s[j][u] = 0.f;
        #pragma unroll
        for (int ks = 0; ks < 8; ks++) {
            #pragma unroll
            for (int j = 0; j < 8; j++) {
                int r = j * 8 + (lane >> 2);
                int c = ks * 8 + (lane & 3);
                unsigned bh[2], bl[2];
                bh[0] = Kh[r*LDQ + c];  bh[1] = Kh[r*LDQ + c + 4];
                bl[0] = Kl[r*LDQ + c];  bl[1] = Kl[r*LDQ + c + 4];
                mma8(s[j], qh[ks], bh);
                mma8(s[j], qh[ks], bl);
                mma8(s[j], ql[ks], bh);
            }
        }

        float mx0 = -1e30f, mx1 = -1e30f;
        #pragma unroll
        for (int j = 0; j < 8; j++) {
            int cb = j * 8 + (lane & 3) * 2;
            float ms0 = Ms[cb], ms1 = Ms[cb + 1];
            s[j][0] = s[j][0] * 0.125f + ms0;
            s[j][1] = s[j][1] * 0.125f + ms1;
            s[j][2] = s[j][2] * 0.125f + ms0;
            s[j][3] = s[j][3] * 0.125f + ms1;
            mx0 = fmaxf(mx0, fmaxf(s[j][0], s[j][1]));
            mx1 = fmaxf(mx1, fmaxf(s[j][2], s[j][3]));
        }
        #pragma unroll
        for (int off = 1; off < 4; off <<= 1) {
            mx0 = fmaxf(mx0, __shfl_xor_sync(0xffffffffu, mx0, off));
            mx1 = fmaxf(mx1, __shfl_xor_sync(0xffffffffu, mx1, off));
        }
        float mn0 = fmaxf(m0r, mx0), mn1 = fmaxf(m1r, mx1);
        float a0 = expf(m0r - mn0),  a1 = expf(m1r - mn1);
        m0r = mn0; m1r = mn1;
        float rs0 = 0.f, rs1 = 0.f;
        #pragma unroll
        for (int j = 0; j < 8; j++) {
            int cb = j * 8 + (lane & 3) * 2;
            float p00 = expf(s[j][0] - mn0);
            float p01 = expf(s[j][1] - mn0);
            float p10 = expf(s[j][2] - mn1);
            float p11 = expf(s[j][3] - mn1);
            rs0 += p00 + p01; rs1 += p10 + p11;
            unsigned hh;
            hh = f2tf(p00); QPh[rr*LDQ + cb]       = hh; QPl[rr*LDQ + cb]       = f2tf(p00 - __uint_as_float(hh));
            hh = f2tf(p01); QPh[rr*LDQ + cb + 1]   = hh; QPl[rr*LDQ + cb + 1]   = f2tf(p01 - __uint_as_float(hh));
            hh = f2tf(p10); QPh[(rr+8)*LDQ + cb]   = hh; QPl[(rr+8)*LDQ + cb]   = f2tf(p10 - __uint_as_float(hh));
            hh = f2tf(p11); QPh[(rr+8)*LDQ + cb+1] = hh; QPl[(rr+8)*LDQ + cb+1] = f2tf(p11 - __uint_as_float(hh));
            o[j][0] *= a0; o[j][1] *= a0; o[j][2] *= a1; o[j][3] *= a1;
        }
        #pragma unroll
        for (int off = 1; off < 4; off <<= 1) {
            rs0 += __shfl_xor_sync(0xffffffffu, rs0, off);
            rs1 += __shfl_xor_sync(0xffffffffu, rs1, off);
        }
        l0 = l0 * a0 + rs0;
        l1 = l1 * a1 + rs1;
        __syncwarp();

        #pragma unroll
        for (int ks = 0; ks < 8; ks++) {
            int c = ks * 8 + (lane & 3);
            unsigned ah[4], al[4];
            ah[0] = QPh[rr*LDQ + c];     ah[1] = QPh[(rr+8)*LDQ + c];
            ah[2] = QPh[rr*LDQ + c + 4]; ah[3] = QPh[(rr+8)*LDQ + c + 4];
            al[0] = QPl[rr*LDQ + c];     al[1] = QPl[(rr+8)*LDQ + c];
            al[2] = QPl[rr*LDQ + c + 4]; al[3] = QPl[(rr+8)*LDQ + c + 4];
            #pragma unroll
            for (int j = 0; j < 8; j++) {
                int n = j * 8 + (lane >> 2);
                unsigned bh[2], bl[2];
                bh[0] = Vh[(ks*8 + (lane&3)) * LDVt + n];
                bh[1] = Vh[(ks*8 + (lane&3) + 4) * LDVt + n];
                bl[0] = Vl[(ks*8 + (lane&3)) * LDVt + n];
                bl[1] = Vl[(ks*8 + (lane&3) + 4) * LDVt + n];
                mma8(o[j], ah, bh);
                mma8(o[j], ah, bl);
                mma8(o[j], al, bh);
            }
        }
    }

    float i0 = 1.f / l0, i1 = 1.f / l1;
    int gq = q0 + rr;
    #pragma unroll
    for (int j = 0; j < 8; j++) {
        int col = h * 64 + j * 8 + (lane & 3) * 2;
        *(float2*)(ctx + (size_t)gq * Dv + col)     = make_float2(o[j][0]*i0, o[j][1]*i0);
        *(float2*)(ctx + (size_t)(gq+8) * Dv + col) = make_float2(o[j][2]*i1, o[j][3]*i1);
    }
}

// ---------------- SimHash codes ----------------
__global__ void coden_kernel()
{
    int idx = blockIdx.x * 256 + threadIdx.x;
    if (idx >= LTv * NCv) return;
    int n = idx & (NCv - 1), l = idx >> 12;
    int code = 0;
    #pragma unroll
    for (int kk = 0; kk < KHv; kk++)
        if (g_projn[(size_t)(l * KHv + kk) * NCv + n] > 0.f) code |= (1 << kk);
    g_coden[l * NCv + n] = code;
}

// fused token codes + histogram (both chunks); hist must be pre-zeroed
__global__ void codet_hist_kernel()
{
    int idx = blockIdx.x * 256 + threadIdx.x;   // LT*NTOK = 32768
    if (idx >= LTv * NTOK) return;
    int tt = idx & (NTOK - 1), l = idx >> 11;
    int code = 0;
    #pragma unroll
    for (int kk = 0; kk < KHv; kk++)
        if (g_projt[(size_t)(l * KHv + kk) * NTOK + tt] > 0.f) code |= (1 << kk);
    int ch = tt >> 10;
    atomicAdd(&g_hist[(ch * LTv + l) * NBv + code], 1);
}

__global__ void tanhpt_kernel()
{
    int idx = blockIdx.x * 256 + threadIdx.x;   // NTOK*LK
    if (idx >= NTOK * LKv) return;
    int t = idx >> 7, lk = idx & 127;
    g_tanhpt[idx] = tanhf(g_projt[(size_t)lk * NTOK + t]);
}

__global__ void score_kernel()
{
    int idx = blockIdx.x * 256 + threadIdx.x;   // 2*NC
    if (idx >= 2 * NCv) return;
    int ch = idx >> 12, n = idx & (NCv - 1);
    const int* hist = g_hist + ch * LTv * NBv;
    int s = 0;
    #pragma unroll
    for (int l = 0; l < LTv; l++) s += hist[l * NBv + g_coden[l * NCv + n]];
    g_score[idx] = s;
}

// ---------------- stable top-S selection (block = chunk) ----------------
__global__ void select_kernel()
{
    __shared__ int ssc[NCv];
    __shared__ int red[1024];
    const int ch = blockIdx.x;
    const int* score = g_score + ch * NCv;
    int* sids = g_sids + ch * SSv;
    int tid = threadIdx.x;
    for (int i = tid; i < NCv; i += 1024) ssc[i] = score[i];
    __syncthreads();

    int lo = 0, hi = LTv * TPPv + 1;
    while (lo + 1 < hi) {
        int mid = (lo + hi) >> 1;
        int c = 0;
        for (int i = tid; i < NCv; i += 1024) c += (ssc[i] >= mid);
        red[tid] = c; __syncthreads();
        for (int st = 512; st > 0; st >>= 1) { if (tid < st) red[tid] += red[tid + st]; __syncthreads(); }
        int tot = red[0]; __syncthreads();
        if (tot >= SSv) lo = mid; else hi = mid;
    }
    int tau = lo;
    int c = 0;
    for (int i = tid; i < NCv; i += 1024) c += (ssc[i] > tau);
    red[tid] = c; __syncthreads();
    for (int st = 512; st > 0; st >>= 1) { if (tid < st) red[tid] += red[tid + st]; __syncthreads(); }
    int m = red[0];
    int need = SSv - m;
    __syncthreads();

    int base = tid * 4;
    int gtp[4], eqp[4];
    int lgt = 0, leq = 0;
    #pragma unroll
    for (int j = 0; j < 4; j++) {
        int sc = ssc[base + j];
        gtp[j] = lgt; eqp[j] = leq;
        lgt += (sc > tau); leq += (sc == tau);
    }
    red[tid] = (lgt << 16) | leq; __syncthreads();
    for (int off = 1; off < 1024; off <<= 1) {
        int vv = (tid >= off) ? red[tid - off] : 0;
        __syncthreads();
        red[tid] += vv;
        __syncthreads();
    }
    int excl = (tid == 0) ? 0 : red[tid - 1];
    int egt = excl >> 16, eeq = excl & 0xffff;
    #pragma unroll
    for (int j = 0; j < 4; j++) {
        int sc = ssc[base + j];
        if (sc > tau)                                sids[egt + gtp[j]] = base + j;
        else if (sc == tau && (eeq + eqp[j]) < need) sids[m + eeq + eqp[j]] = base + j;
    }
}

// ---------------- gathers (both chunks) ----------------
__global__ void gather_kernel(const float* __restrict__ W1, const float* __restrict__ b1)
{
    int idx = blockIdx.x * 256 + threadIdx.x;   // 2*SS*D
    if (idx >= 2 * SSv * Dv) return;
    int ch = idx >> 20;
    int s = (idx >> 10) & 1023, dcol = idx & 1023;
    int row = g_sids[ch * SSv + s];
    g_w1s[idx] = W1[(size_t)row * Dv + dcol];
    if (dcol == 0) g_b1s[ch * SSv + s] = b1[row];
}
__global__ void gatherT_kernel(const float* __restrict__ W2)
{
    __shared__ float tile[32][33];
    int ch = blockIdx.x / (SSv / 32);
    int s0 = (blockIdx.x % (SSv / 32)) * 32, d0 = blockIdx.y * 32;
    int tx = threadIdx.x & 31, ty8 = threadIdx.x >> 5;
    for (int r = ty8; r < 32; r += 8) {
        int row = g_sids[ch * SSv + s0 + r];
        tile[r][tx] = W2[(size_t)row * Dv + d0 + tx];
    }
    __syncthreads();
    float* dst = g_w2sT + (size_t)ch * Dv * SSv;
    for (int r = ty8; r < 32; r += 8)
        dst[(size_t)(d0 + r) * SSv + s0 + tx] = tile[tx][r];
}
__global__ void tanhpns_kernel()
{
    int idx = blockIdx.x * 256 + threadIdx.x;   // 2*SS*LK
    if (idx >= 2 * SSv * LKv) return;
    int ch = idx >> 17;
    int s = (idx >> 7) & 1023, lk = idx & 127;
    int row = g_sids[ch * SSv + s];
    g_tanhpns[idx] = tanhf(g_projn[(size_t)lk * NCv + row]);
}

// ---------------- triplet loss (warp per token, all tokens) ----------------
__global__ void __launch_bounds__(256)
triplet2()
{
    __shared__ float vals[8][1024];
    int w = threadIdx.x >> 5, lane = threadIdx.x & 31;
    int t = blockIdx.x * 8 + w;                  // global token 0..2047
    int ch = t >> 10;
    const float* lrow = g_logits + (size_t)t * SSv;
    const float* tpns = g_tanhpns + (size_t)ch * SSv * LKv;

    float apos = 0.f, aneg = 0.f;
    for (int phase = 0; phase < 2; phase++) {
        for (int i = lane; i < 256; i += 32)
            ((float4*)vals[w])[i] = ((const float4*)lrow)[i];
        __syncwarp();
        float sv[4] = {0.f, 0.f, 0.f, 0.f};
        for (int it = 0; it < PPv; it++) {
            float bv = (phase == 0) ? -1e30f : 1e30f;
            int bi = 1 << 30;
            #pragma unroll
            for (int qd = 0; qd < 32; qd++) {
                int i = lane + (qd << 5);
                float x = vals[w][i];
                bool better = (phase == 0) ? (x > bv) : (x < bv);
                if (better) { bv = x; bi = i; }
            }
            #pragma unroll
            for (int off = 16; off > 0; off >>= 1) {
                float ov = __shfl_xor_sync(0xffffffffu, bv, off);
                int   oi = __shfl_xor_sync(0xffffffffu, bi, off);
                bool take = (phase == 0)
                    ? (ov > bv || (ov == bv && oi < bi))
                    : (ov < bv || (ov == bv && oi < bi));
                if (take) { bv = ov; bi = oi; }
            }
            #pragma unroll
            for (int c2 = 0; c2 < 4; c2++)
                sv[c2] += tpns[(size_t)bi * LKv + lane + 32 * c2];
            if (lane == 0) vals[w][bi] = (phase == 0) ? -1e30f : 1e30f;
            __syncwarp();
        }
        float a = 0.f;
        #pragma unroll
        for (int c2 = 0; c2 < 4; c2++)
            a += sv[c2] * g_tanhpt[(size_t)t * LKv + lane + 32 * c2];
        #pragma unroll
        for (int off = 16; off > 0; off >>= 1)
            a += __shfl_xor_sync(0xffffffffu, a, off);
        a *= 1.0f / (128.0f * 64.0f);
        if (phase == 0) apos = a; else aneg = a;
    }
    if (lane == 0) g_trip[t] = fmaxf(aneg - apos + 0.5f, 0.f);
}

__global__ void trip_reduce(float* __restrict__ outp)
{
    __shared__ float red[1024];
    int tid = threadIdx.x;
    red[tid] = g_trip[tid] + g_trip[tid + 1024];
    __syncthreads();
    for (int st = 512; st > 0; st >>= 1) { if (tid < st) red[tid] += red[tid + st]; __syncthreads(); }
    if (tid == 0) *outp = red[0] * (1.0f / 2048.0f);
}

// ---------------- host ----------------
extern "C" void kernel_launch(void* const* d_in, const int* in_sizes, int n_in,
                              void* d_out, int out_size)
{
    const float* hidden = (const float*)d_in[0];
    const float* amask  = (const float*)d_in[1];
    const float* ln1_g  = (const float*)d_in[2];
    const float* ln1_b  = (const float*)d_in[3];
    const float* Wq     = (const float*)d_in[4];
    const float* bq     = (const float*)d_in[5];
    const float* Wk     = (const float*)d_in[6];
    const float* bk     = (const float*)d_in[7];
    const float* Wv     = (const float*)d_in[8];
    const float* bv     = (const float*)d_in[9];
    const float* Wo     = (const float*)d_in[10];
    const float* bo     = (const float*)d_in[11];
    const float* ln2_g  = (const float*)d_in[12];
    const float* ln2_b  = (const float*)d_in[13];
    const float* W1     = (const float*)d_in[14];
    const float* b1     = (const float*)d_in[15];
    const float* Whash  = (const float*)d_in[16];
    const float* W2     = (const float*)d_in[17];
    const float* b2     = (const float*)d_in[18];
    float* out = (float*)d_out;

    float *xln, *q, *k, *v, *ctx, *attn, *normed, *projn, *projt;
    float *w1s, *w2sT, *b1s, *logits, *acts;
    int* histp;
    cudaGetSymbolAddress((void**)&xln,    g_xln);
    cudaGetSymbolAddress((void**)&q,      g_q);
    cudaGetSymbolAddress((void**)&k,      g_k);
    cudaGetSymbolAddress((void**)&v,      g_v);
    cudaGetSymbolAddress((void**)&ctx,    g_ctx);
    cudaGetSymbolAddress((void**)&attn,   g_attn);
    cudaGetSymbolAddress((void**)&normed, g_normed);
    cudaGetSymbolAddress((void**)&projn,  g_projn);
    cudaGetSymbolAddress((void**)&projt,  g_projt);
    cudaGetSymbolAddress((void**)&w1s,    g_w1s);
    cudaGetSymbolAddress((void**)&w2sT,   g_w2sT);
    cudaGetSymbolAddress((void**)&b1s,    g_b1s);
    cudaGetSymbolAddress((void**)&logits, g_logits);
    cudaGetSymbolAddress((void**)&acts,   g_acts);
    cudaGetSymbolAddress((void**)&histp,  g_hist);

    const int SM3  = (128 + 128) * 36 * 4 * 2;   // 73728
    const int SM1  = (64 + 128) * 36 * 4;        // 27648
    const int SMAT = (4*64*LDQ + 2*64*LDVt) * 4 + 64*4;
    cudaFuncSetAttribute((const void*)mma_nt<3,0,true,false,128,128>,
                         cudaFuncAttributeMaxDynamicSharedMemorySize, SM3);
    cudaFuncSetAttribute((const void*)mma_nt<3,0,true,true,128,128>,
                         cudaFuncAttributeMaxDynamicSharedMemorySize, SM3);
    cudaFuncSetAttribute((const void*)mma_nt<1,1,true,false,64,128>,
                         cudaFuncAttributeMaxDynamicSharedMemorySize, SM1);
    cudaFuncSetAttribute((const void*)mma_nt<1,0,true,true,64,128>,
                         cudaFuncAttributeMaxDynamicSharedMemorySize, SM1);
    cudaFuncSetAttribute((const void*)attn3,
                         cudaFuncAttributeMaxDynamicSharedMemorySize, SMAT);

    P3 nul3 = {nullptr, nullptr, nullptr};

    // ---- attention path ----
    ln_kernel<<<SQv, 256>>>(hidden, ln1_g, ln1_b, xln);
    // fused QKV: grid.z selects weight/bias/output
    {
        P3 Bqkv = {Wq, Wk, Wv};
        P3 bqkv = {bq, bk, bv};
        O3 Cqkv = {q, k, v};
        mma_nt<3,0,true,false,128,128><<<dim3(8,16,3), 256, SM3>>>(
            xln, Bqkv, bqkv, nullptr, Cqkv, nullptr,
            0, 0, 0, 0, 0, 0, SQv, Dv, Dv);
    }
    attn3<<<dim3(SQv/64, Hv), 128, SMAT>>>(q, k, v, amask, ctx);
    {
        P3 Bo = {Wo, Wo, Wo};
        P3 bo3 = {bo, bo, bo};
        O3 Ca = {attn, attn, attn};
        mma_nt<3,0,true,true,128,128><<<dim3(8,16,1), 256, SM3>>>(
            ctx, Bo, bo3, hidden, Ca, nullptr,
            0, 0, 0, 0, 0, 0, SQv, Dv, Dv);
    }

    // ---- FFN prep ----
    ln_kernel<<<SQv, 256>>>(attn, ln2_g, ln2_b, normed);
    gemm_nt<false><<<dim3(NCv/64, LKv/64), 256>>>(Whash, W1, nullptr, projn, LKv, NCv, Dv);
    coden_kernel<<<(LTv * NCv) / 256, 256>>>();

    // ---- LSH FFN, both chunks fused ----
    // proj_t for all 2048 tokens in one GEMM: [LK, NTOK]
    gemm_nt<false><<<dim3(NTOK/64, LKv/64), 256>>>(Whash, normed, nullptr, projt, LKv, NTOK, Dv);
    cudaMemsetAsync(histp, 0, 2 * LTv * NBv * sizeof(int), 0);
    codet_hist_kernel<<<(LTv * NTOK) / 256, 256>>>();
    tanhpt_kernel<<<(NTOK * LKv) / 256, 256>>>();
    score_kernel<<<(2 * NCv) / 256, 256>>>();
    select_kernel<<<2, 1024>>>();
    gather_kernel<<<(2 * SSv * Dv) / 256, 256>>>(W1, b1);
    gatherT_kernel<<<dim3(2 * SSv / 32, Dv / 32), 256>>>(W2);
    tanhpns_kernel<<<(2 * SSv * LKv) / 256, 256>>>();

    // logits + fused GELU, both chunks (z-strided)
    {
        P3 Bl = {w1s, w1s, w1s};
        P3 bl = {b1s, b1s, b1s};
        O3 Cl = {logits, logits, logits};
        mma_nt<1,1,true,false,64,128><<<dim3(SSv/128, TPPv/64, 2), 256, SM1>>>(
            normed, Bl, bl, nullptr, Cl, acts,
            (long)TPPv*Dv, (long)SSv*Dv, (long)SSv, 0, (long)TPPv*SSv, (long)TPPv*SSv,
            TPPv, SSv, Dv);
    }
    triplet2<<<NTOK/8, 256>>>();
    // out = acts @ W2s^T + b2 + attn residual, both chunks
    {
        P3 Bw2 = {w2sT, w2sT, w2sT};
        P3 bb2 = {b2, b2, b2};
        O3 Co = {out, out, out};
        mma_nt<1,0,true,true,64,128><<<dim3(Dv/128, TPPv/64, 2), 256, SM1>>>(
            acts, Bw2, bb2, attn, Co, nullptr,
            (long)TPPv*SSv, (long)Dv*SSv, 0, (long)TPPv*Dv, (long)TPPv*Dv, 0,
            TPPv, Dv, SSv);
    }

    // ---- scalar output ----
    trip_reduce<<<1, 1024>>>(out + (size_t)SQv * Dv);
}

// round 8
// speedup vs baseline: 1.5444x; 1.5444x over previous
#include <cuda_runtime.h>
#include <math.h>
#include <stddef.h>

// ---------------- problem constants ----------------
#define SQv   2048
#define Dv    1024
#define Hv    16
#define DHv   64
#define NCv   4096
#define LTv   16      // tables
#define KHv   8       // hash funcs per table
#define LKv   128     // LT*KH
#define NBv   256     // buckets
#define TPPv  1024
#define SSv   1024    // sample budget
#define PPv   64
#define NTOK  2048

// ---------------- device scratch ----------------
__device__ __align__(16) float    g_xln   [SQv*Dv];
__device__ __align__(16) unsigned g_qh    [SQv*Dv];
__device__ __align__(16) unsigned g_ql    [SQv*Dv];
__device__ __align__(16) unsigned g_kh    [SQv*Dv];
__device__ __align__(16) unsigned g_kl    [SQv*Dv];
__device__ __align__(16) unsigned g_vh    [SQv*Dv];
__device__ __align__(16) unsigned g_vl    [SQv*Dv];
__device__ __align__(16) float    g_ctx   [SQv*Dv];
__device__ __align__(16) float    g_attn  [SQv*Dv];
__device__ __align__(16) float    g_normed[SQv*Dv];
__device__ __align__(16) float    g_msk   [SQv];
__device__ __align__(16) float    g_projn [LKv*NCv];
__device__ __align__(16) float    g_projt [LKv*NTOK];
__device__ __align__(16) float    g_tanhpt[NTOK*LKv];
__device__ __align__(16) float    g_tanhpns[2*SSv*LKv];
__device__ __align__(16) float    g_w1s   [2*SSv*Dv];
__device__ __align__(16) float    g_w2sT  [2*(size_t)Dv*SSv];
__device__ __align__(16) float    g_b1s   [2*SSv];
__device__ __align__(16) float    g_logits[NTOK*SSv];
__device__ __align__(16) float    g_acts  [NTOK*SSv];
__device__ __align__(16) float    g_trip  [NTOK];
__device__ int g_coden[LTv*NCv];
__device__ int g_hist [2*LTv*NBv];
__device__ int g_score[2*NCv];
__device__ int g_sids [2*SSv];

// ---------------- helpers ----------------
__device__ __forceinline__ unsigned f2tf(float x){
    unsigned u; asm("cvt.rna.tf32.f32 %0, %1;" : "=r"(u) : "f"(x)); return u;
}
__device__ __forceinline__ void mma8(float* d, const unsigned* a, const unsigned* b){
    asm volatile("mma.sync.aligned.m16n8k8.row.col.f32.tf32.tf32.f32 "
        "{%0,%1,%2,%3},{%4,%5,%6,%7},{%8,%9},{%0,%1,%2,%3};"
        : "+f"(d[0]), "+f"(d[1]), "+f"(d[2]), "+f"(d[3])
        : "r"(a[0]), "r"(a[1]), "r"(a[2]), "r"(a[3]), "r"(b[0]), "r"(b[1]));
}
__device__ __forceinline__ float gelu_exact(float x){
    return 0.5f * x * (1.f + erff(x * 0.70710678118654752f));
}
__device__ __forceinline__ unsigned s2u(const void* p){
    return (unsigned)__cvta_generic_to_shared(p);
}
__device__ __forceinline__ void cpa16(unsigned dst, const void* src){
    asm volatile("cp.async.ca.shared.global [%0], [%1], 16;" :: "r"(dst), "l"(src));
}
__device__ __forceinline__ void cpa_commit(){ asm volatile("cp.async.commit_group;"); }
__device__ __forceinline__ void cpa_wait0(){ asm volatile("cp.async.wait_group 0;" ::: "memory"); }

// ---------------- LayerNorm ----------------
__global__ void ln_kernel(const float* __restrict__ x, const float* __restrict__ g,
                          const float* __restrict__ b, float* __restrict__ y)
{
    int row = blockIdx.x;
    const float* xr = x + (size_t)row * Dv;
    __shared__ float red[256];
    int tid = threadIdx.x;
    float s = 0.f, ss = 0.f;
    for (int i = tid; i < Dv; i += 256) { float v = xr[i]; s += v; ss += v * v; }
    red[tid] = s; __syncthreads();
    for (int st = 128; st > 0; st >>= 1) { if (tid < st) red[tid] += red[tid + st]; __syncthreads(); }
    float mean = red[0] / Dv;
    __syncthreads();
    red[tid] = ss; __syncthreads();
    for (int st = 128; st > 0; st >>= 1) { if (tid < st) red[tid] += red[tid + st]; __syncthreads(); }
    float var = red[0] / Dv - mean * mean;
    float inv = rsqrtf(var + 1e-12f);
    float* yr = y + (size_t)row * Dv;
    for (int i = tid; i < Dv; i += 256) yr[i] = (xr[i] - mean) * inv * g[i] + b[i];
}

__global__ void msk_kernel(const float* __restrict__ mask)
{
    int i = blockIdx.x * 256 + threadIdx.x;
    if (i < SQv) g_msk[i] = -1000.f * (1.f - mask[i]);
}

// ---------------- TF32 tensor-core GEMM NT (round-4 form) ----------------
// EPI=0: write C fp32. EPI=1: C fp32 + gelu(C) into C2. EPI=2: write hi->C, lo->C2 (u32).
template<int SPLIT, int EPI, bool BIAS, bool RES, int BM_, int BN_>
__global__ void __launch_bounds__(256, 1)
mma_nt(const float* __restrict__ A, const float* __restrict__ B,
       const float* __restrict__ bias, const float* __restrict__ res,
       float* __restrict__ C, float* __restrict__ C2, int M, int N, int K)
{
    constexpr int BK = 32, LD = 36;
    constexpr int WTM = BM_ / 2, WTN = BN_ / 4;
    constexpr int MT = WTM / 16, NT = WTN / 8;
    extern __shared__ unsigned sm[];
    unsigned* Ah = sm;
    unsigned* Bh = Ah + BM_ * LD;
    unsigned* Al = (SPLIT == 3) ? Bh + BN_ * LD : Ah;
    unsigned* Bl = (SPLIT == 3) ? Al + BM_ * LD : Bh;

    const int tid = threadIdx.x;
    const int lane = tid & 31, wid = tid >> 5;
    const int wm = wid & 1, wn = wid >> 1;
    const int m0 = blockIdx.y * BM_, n0 = blockIdx.x * BN_;

    constexpr int PA = BM_ / 32;
    constexpr int PB = BN_ / 32;
    const int lrw = tid >> 3;
    const int lcc = (tid & 7) * 4;

    float4 pa[PA], pb[PB];
    float acc[MT][NT][4];
    #pragma unroll
    for (int i = 0; i < MT; i++)
        #pragma unroll
        for (int j = 0; j < NT; j++)
            #pragma unroll
            for (int u = 0; u < 4; u++) acc[i][j][u] = 0.f;

    #pragma unroll
    for (int p = 0; p < PA; p++)
        pa[p] = *(const float4*)(A + (size_t)(m0 + p*32 + lrw) * K + lcc);
    #pragma unroll
    for (int p = 0; p < PB; p++)
        pb[p] = *(const float4*)(B + (size_t)(n0 + p*32 + lrw) * K + lcc);

    const int ntiles = K / BK;
    for (int kt = 0; kt < ntiles; kt++) {
        __syncthreads();
        #pragma unroll
        for (int p = 0; p < PA; p++) {
            float vv[4] = {pa[p].x, pa[p].y, pa[p].z, pa[p].w};
            #pragma unroll
            for (int i = 0; i < 4; i++) {
                unsigned h = f2tf(vv[i]);
                Ah[(p*32 + lrw) * LD + lcc + i] = h;
                if (SPLIT == 3)
                    Al[(p*32 + lrw) * LD + lcc + i] = f2tf(vv[i] - __uint_as_float(h));
            }
        }
        #pragma unroll
        for (int p = 0; p < PB; p++) {
            float vv[4] = {pb[p].x, pb[p].y, pb[p].z, pb[p].w};
            #pragma unroll
            for (int i = 0; i < 4; i++) {
                unsigned h = f2tf(vv[i]);
                Bh[(p*32 + lrw) * LD + lcc + i] = h;
                if (SPLIT == 3)
                    Bl[(p*32 + lrw) * LD + lcc + i] = f2tf(vv[i] - __uint_as_float(h));
            }
        }
        __syncthreads();
        if (kt + 1 < ntiles) {
            const float* An = A + (size_t)(kt + 1) * BK;
            const float* Bn = B + (size_t)(kt + 1) * BK;
            #pragma unroll
            for (int p = 0; p < PA; p++)
                pa[p] = *(const float4*)(An + (size_t)(m0 + p*32 + lrw) * K + lcc);
            #pragma unroll
            for (int p = 0; p < PB; p++)
                pb[p] = *(const float4*)(Bn + (size_t)(n0 + p*32 + lrw) * K + lcc);
        }
        #pragma unroll
        for (int ks = 0; ks < 4; ks++) {
            unsigned ah[MT][4], al[MT][4], bh[NT][2], bl[NT][2];
            #pragma unroll
            for (int i = 0; i < MT; i++) {
                int r = wm * WTM + i * 16 + (lane >> 2);
                int c = ks * 8 + (lane & 3);
                ah[i][0] = Ah[r*LD + c];       ah[i][1] = Ah[(r+8)*LD + c];
                ah[i][2] = Ah[r*LD + c + 4];   ah[i][3] = Ah[(r+8)*LD + c + 4];
                if (SPLIT == 3) {
                    al[i][0] = Al[r*LD + c];     al[i][1] = Al[(r+8)*LD + c];
                    al[i][2] = Al[r*LD + c + 4]; al[i][3] = Al[(r+8)*LD + c + 4];
                }
            }
            #pragma unroll
            for (int j = 0; j < NT; j++) {
                int r = wn * WTN + j * 8 + (lane >> 2);
                int c = ks * 8 + (lane & 3);
                bh[j][0] = Bh[r*LD + c];  bh[j][1] = Bh[r*LD + c + 4];
                if (SPLIT == 3) {
                    bl[j][0] = Bl[r*LD + c];  bl[j][1] = Bl[r*LD + c + 4];
                }
            }
            #pragma unroll
            for (int i = 0; i < MT; i++)
                #pragma unroll
                for (int j = 0; j < NT; j++) {
                    mma8(acc[i][j], ah[i], bh[j]);
                    if (SPLIT == 3) {
                        mma8(acc[i][j], ah[i], bl[j]);
                        mma8(acc[i][j], al[i], bh[j]);
                    }
                }
        }
    }
    #pragma unroll
    for (int i = 0; i < MT; i++) {
        #pragma unroll
        for (int j = 0; j < NT; j++) {
            int r = m0 + wm * WTM + i * 16 + (lane >> 2);
            int c = n0 + wn * WTN + j * 8 + (lane & 3) * 2;
            float v00 = acc[i][j][0], v01 = acc[i][j][1];
            float v10 = acc[i][j][2], v11 = acc[i][j][3];
            if (BIAS) { float b0 = bias[c], b1 = bias[c+1]; v00 += b0; v01 += b1; v10 += b0; v11 += b1; }
            if (RES) {
                v00 += res[(size_t)r*N + c];     v01 += res[(size_t)r*N + c + 1];
                v10 += res[(size_t)(r+8)*N + c]; v11 += res[(size_t)(r+8)*N + c + 1];
            }
            if (EPI == 2) {
                unsigned* Chi = (unsigned*)C;
                unsigned* Clo = (unsigned*)C2;
                unsigned h00 = f2tf(v00), h01 = f2tf(v01), h10 = f2tf(v10), h11 = f2tf(v11);
                *(uint2*)(Chi + (size_t)r*N + c)     = make_uint2(h00, h01);
                *(uint2*)(Chi + (size_t)(r+8)*N + c) = make_uint2(h10, h11);
                *(uint2*)(Clo + (size_t)r*N + c)     =
                    make_uint2(f2tf(v00 - __uint_as_float(h00)), f2tf(v01 - __uint_as_float(h01)));
                *(uint2*)(Clo + (size_t)(r+8)*N + c) =
                    make_uint2(f2tf(v10 - __uint_as_float(h10)), f2tf(v11 - __uint_as_float(h11)));
            } else {
                *(float2*)(C + (size_t)r*N + c)     = make_float2(v00, v01);
                *(float2*)(C + (size_t)(r+8)*N + c) = make_float2(v10, v11);
                if (EPI == 1) {
                    *(float2*)(C2 + (size_t)r*N + c)     = make_float2(gelu_exact(v00), gelu_exact(v01));
                    *(float2*)(C2 + (size_t)(r+8)*N + c) = make_float2(gelu_exact(v10), gelu_exact(v11));
                }
            }
        }
    }
}

// ---------------- exact-fp32 GEMM NT (hash projections only) ----------------
template<bool HAS_BIAS>
__global__ void gemm_nt(const float* __restrict__ A, const float* __restrict__ Bm,
                        const float* __restrict__ bias,
                        float* __restrict__ C, int M, int N, int Kd)
{
    __shared__ float As[16][64];
    __shared__ float Bs[16][64];
    int tid = threadIdx.x;
    int tx = tid & 15, ty = tid >> 4;
    int m0 = blockIdx.y * 64, n0 = blockIdx.x * 64;
    float acc[4][4] = {};
    for (int k0 = 0; k0 < Kd; k0 += 16) {
        int idx = tid * 4;
        int r = idx >> 4, kk = idx & 15;
        float4 av = *(const float4*)(A  + (size_t)(m0 + r) * Kd + k0 + kk);
        As[kk+0][r] = av.x; As[kk+1][r] = av.y; As[kk+2][r] = av.z; As[kk+3][r] = av.w;
        float4 bv = *(const float4*)(Bm + (size_t)(n0 + r) * Kd + k0 + kk);
        Bs[kk+0][r] = bv.x; Bs[kk+1][r] = bv.y; Bs[kk+2][r] = bv.z; Bs[kk+3][r] = bv.w;
        __syncthreads();
        #pragma unroll
        for (int q = 0; q < 16; q++) {
            float a[4], b[4];
            #pragma unroll
            for (int i = 0; i < 4; i++) a[i] = As[q][ty*4+i];
            #pragma unroll
            for (int j = 0; j < 4; j++) b[j] = Bs[q][tx*4+j];
            #pragma unroll
            for (int i = 0; i < 4; i++)
                #pragma unroll
                for (int j = 0; j < 4; j++)
                    acc[i][j] += a[i] * b[j];
        }
        __syncthreads();
    }
    #pragma unroll
    for (int i = 0; i < 4; i++) {
        int m = m0 + ty*4 + i;
        #pragma unroll
        for (int j = 0; j < 4; j++) {
            int n = n0 + tx*4 + j;
            float v = acc[i][j];
            if (HAS_BIAS) v += bias[n];
            C[(size_t)m * N + n] = v;
        }
    }
}

// ---------------- attention: 3xTF32 flash on pre-split inputs ----------------
#define LDQ 68
#define LDVt 72
__global__ void __launch_bounds__(128, 2)
attn4(const unsigned* __restrict__ qh_g, const unsigned* __restrict__ ql_g,
      const unsigned* __restrict__ kh_g, const unsigned* __restrict__ kl_g,
      const unsigned* __restrict__ vh_g, const unsigned* __restrict__ vl_g,
      float* __restrict__ ctx)
{
    extern __shared__ unsigned sm[];
    unsigned* QPh = sm;
    unsigned* QPl = QPh + 64*LDQ;
    unsigned* Kh  = QPl + 64*LDQ;
    unsigned* Kl  = Kh  + 64*LDQ;
    unsigned* Vh  = Kl  + 64*LDQ;
    unsigned* Vl  = Vh  + 64*LDVt;
    float*    Ms  = (float*)(Vl + 64*LDVt);

    const int tid = threadIdx.x;
    const int lane = tid & 31, w = tid >> 5;
    const int h = blockIdx.y, q0 = blockIdx.x * 64;
    const int rr = w * 16 + (lane >> 2);

    const unsigned uQPh = s2u(QPh), uQPl = s2u(QPl);
    const unsigned uKh = s2u(Kh), uKl = s2u(Kl), uVh = s2u(Vh), uVl = s2u(Vl);
    const unsigned uMs = s2u(Ms);

    // ---- Q tiles via cp.async ----
    #pragma unroll
    for (int p = 0; p < 8; p++) {
        int idx = tid + p * 128;
        int row = idx >> 4, c4 = (idx & 15) * 4;
        size_t gof = (size_t)(q0 + row) * Dv + h * 64 + c4;
        unsigned sof = (row * LDQ + c4) * 4;
        cpa16(uQPh + sof, qh_g + gof);
        cpa16(uQPl + sof, ql_g + gof);
    }
    cpa_commit(); cpa_wait0();
    __syncthreads();

    unsigned qh[8][4], ql[8][4];
    #pragma unroll
    for (int ks = 0; ks < 8; ks++) {
        int c = ks * 8 + (lane & 3);
        qh[ks][0] = QPh[rr*LDQ + c];       qh[ks][1] = QPh[(rr+8)*LDQ + c];
        qh[ks][2] = QPh[rr*LDQ + c + 4];   qh[ks][3] = QPh[(rr+8)*LDQ + c + 4];
        ql[ks][0] = QPl[rr*LDQ + c];       ql[ks][1] = QPl[(rr+8)*LDQ + c];
        ql[ks][2] = QPl[rr*LDQ + c + 4];   ql[ks][3] = QPl[(rr+8)*LDQ + c + 4];
    }

    float o[8][4];
    #pragma unroll
    for (int j = 0; j < 8; j++)
        #pragma unroll
        for (int u = 0; u < 4; u++) o[j][u] = 0.f;
    float m0r = -1e30f, m1r = -1e30f, l0 = 0.f, l1 = 0.f;

    for (int kt = 0; kt < SQv / 64; kt++) {
        int k0 = kt * 64;
        __syncthreads();   // previous tile fully consumed
        #pragma unroll
        for (int p = 0; p < 8; p++) {
            int idx = tid + p * 128;
            int row = idx >> 4, c4 = (idx & 15) * 4;
            size_t gof = (size_t)(k0 + row) * Dv + h * 64 + c4;
            unsigned sK = (row * LDQ + c4) * 4;
            unsigned sV = (row * LDVt + c4) * 4;
            cpa16(uKh + sK, kh_g + gof);
            cpa16(uKl + sK, kl_g + gof);
            cpa16(uVh + sV, vh_g + gof);
            cpa16(uVl + sV, vl_g + gof);
        }
        if (tid < 16) cpa16(uMs + tid * 16, g_msk + k0 + tid * 4);
        cpa_commit(); cpa_wait0();
        __syncthreads();

        // S = Q K^T (3x split)
        float s[8][4];
        #pragma unroll
        for (int j = 0; j < 8; j++)
            #pragma unroll
            for (int u = 0; u < 4; u++) s[j][u] = 0.f;
        #pragma unroll
        for (int ks = 0; ks < 8; ks++) {
            #pragma unroll
            for (int j = 0; j < 8; j++) {
                int r = j * 8 + (lane >> 2);
                int c = ks * 8 + (lane & 3);
                unsigned bh[2], bl[2];
                bh[0] = Kh[r*LDQ + c];  bh[1] = Kh[r*LDQ + c + 4];
                bl[0] = Kl[r*LDQ + c];  bl[1] = Kl[r*LDQ + c + 4];
                mma8(s[j], qh[ks], bh);
                mma8(s[j], qh[ks], bl);
                mma8(s[j], ql[ks], bh);
            }
        }

        float mx0 = -1e30f, mx1 = -1e30f;
        #pragma unroll
        for (int j = 0; j < 8; j++) {
            int cb = j * 8 + (lane & 3) * 2;
            float ms0 = Ms[cb], ms1 = Ms[cb + 1];
            s[j][0] = s[j][0] * 0.125f + ms0;
            s[j][1] = s[j][1] * 0.125f + ms1;
            s[j][2] = s[j][2] * 0.125f + ms0;
            s[j][3] = s[j][3] * 0.125f + ms1;
            mx0 = fmaxf(mx0, fmaxf(s[j][0], s[j][1]));
            mx1 = fmaxf(mx1, fmaxf(s[j][2], s[j][3]));
        }
        #pragma unroll
        for (int off = 1; off < 4; off <<= 1) {
            mx0 = fmaxf(mx0, __shfl_xor_sync(0xffffffffu, mx0, off));
            mx1 = fmaxf(mx1, __shfl_xor_sync(0xffffffffu, mx1, off));
        }
        float mn0 = fmaxf(m0r, mx0), mn1 = fmaxf(m1r, mx1);
        float a0 = expf(m0r - mn0),  a1 = expf(m1r - mn1);
        m0r = mn0; m1r = mn1;
        float rs0 = 0.f, rs1 = 0.f;
        #pragma unroll
        for (int j = 0; j < 8; j++) {
            int cb = j * 8 + (lane & 3) * 2;
            float p00 = expf(s[j][0] - mn0);
            float p01 = expf(s[j][1] - mn0);
            float p10 = expf(s[j][2] - mn1);
            float p11 = expf(s[j][3] - mn1);
            rs0 += p00 + p01; rs1 += p10 + p11;
            unsigned hh;
            hh = f2tf(p00); QPh[rr*LDQ + cb]       = hh; QPl[rr*LDQ + cb]       = f2tf(p00 - __uint_as_float(hh));
            hh = f2tf(p01); QPh[rr*LDQ + cb + 1]   = hh; QPl[rr*LDQ + cb + 1]   = f2tf(p01 - __uint_as_float(hh));
            hh = f2tf(p10); QPh[(rr+8)*LDQ + cb]   = hh; QPl[(rr+8)*LDQ + cb]   = f2tf(p10 - __uint_as_float(hh));
            hh = f2tf(p11); QPh[(rr+8)*LDQ + cb+1] = hh; QPl[(rr+8)*LDQ + cb+1] = f2tf(p11 - __uint_as_float(hh));
            o[j][0] *= a0; o[j][1] *= a0; o[j][2] *= a1; o[j][3] *= a1;
        }
        #pragma unroll
        for (int off = 1; off < 4; off <<= 1) {
            rs0 += __shfl_xor_sync(0xffffffffu, rs0, off);
            rs1 += __shfl_xor_sync(0xffffffffu, rs1, off);
        }
        l0 = l0 * a0 + rs0;
        l1 = l1 * a1 + rs1;
        __syncwarp();

        // O += P V (3x split); P rows are warp-private
        #pragma unroll
        for (int ks = 0; ks < 8; ks++) {
            int c = ks * 8 + (lane & 3);
            unsigned ah[4], al[4];
            ah[0] = QPh[rr*LDQ + c];     ah[1] = QPh[(rr+8)*LDQ + c];
            ah[2] = QPh[rr*LDQ + c + 4]; ah[3] = QPh[(rr+8)*LDQ + c + 4];
            al[0] = QPl[rr*LDQ + c];     al[1] = QPl[(rr+8)*LDQ + c];
            al[2] = QPl[rr*LDQ + c + 4]; al[3] = QPl[(rr+8)*LDQ + c + 4];
            #pragma unroll
            for (int j = 0; j < 8; j++) {
                int n = j * 8 + (lane >> 2);
                unsigned bh[2], bl[2];
                bh[0] = Vh[(ks*8 + (lane&3)) * LDVt + n];
                bh[1] = Vh[(ks*8 + (lane&3) + 4) * LDVt + n];
                bl[0] = Vl[(ks*8 + (lane&3)) * LDVt + n];
                bl[1] = Vl[(ks*8 + (lane&3) + 4) * LDVt + n];
                mma8(o[j], ah, bh);
                mma8(o[j], ah, bl);
                mma8(o[j], al, bh);
            }
        }
    }

    float i0 = 1.f / l0, i1 = 1.f / l1;
    int gq = q0 + rr;
    #pragma unroll
    for (int j = 0; j < 8; j++) {
        int col = h * 64 + j * 8 + (lane & 3) * 2;
        *(float2*)(ctx + (size_t)gq * Dv + col)     = make_float2(o[j][0]*i0, o[j][1]*i0);
        *(float2*)(ctx + (size_t)(gq+8) * Dv + col) = make_float2(o[j][2]*i1, o[j][3]*i1);
    }
}

// ---------------- SimHash codes ----------------
__global__ void coden_kernel()
{
    int idx = blockIdx.x * 256 + threadIdx.x;
    if (idx >= LTv * NCv) return;
    int n = idx & (NCv - 1), l = idx >> 12;
    int code = 0;
    #pragma unroll
    for (int kk = 0; kk < KHv; kk++)
        if (g_projn[(size_t)(l * KHv + kk) * NCv + n] > 0.f) code |= (1 << kk);
    g_coden[l * NCv + n] = code;
}

// fused token codes + histogram (both chunks); hist pre-zeroed
__global__ void codet_hist_kernel()
{
    int idx = blockIdx.x * 256 + threadIdx.x;   // LT*NTOK
    if (idx >= LTv * NTOK) return;
    int tt = idx & (NTOK - 1), l = idx >> 11;
    int code = 0;
    #pragma unroll
    for (int kk = 0; kk < KHv; kk++)
        if (g_projt[(size_t)(l * KHv + kk) * NTOK + tt] > 0.f) code |= (1 << kk);
    int ch = tt >> 10;
    atomicAdd(&g_hist[(ch * LTv + l) * NBv + code], 1);
}

__global__ void tanhpt_kernel()
{
    int idx = blockIdx.x * 256 + threadIdx.x;   // NTOK*LK
    if (idx >= NTOK * LKv) return;
    int t = idx >> 7, lk = idx & 127;
    g_tanhpt[idx] = tanhf(g_projt[(size_t)lk * NTOK + t]);
}

__global__ void score_kernel()
{
    int idx = blockIdx.x * 256 + threadIdx.x;   // 2*NC
    if (idx >= 2 * NCv) return;
    int ch = idx >> 12, n = idx & (NCv - 1);
    const int* hist = g_hist + ch * LTv * NBv;
    int s = 0;
    #pragma unroll
    for (int l = 0; l < LTv; l++) s += hist[l * NBv + g_coden[l * NCv + n]];
    g_score[idx] = s;
}

// ---------------- stable top-S selection (block = chunk) ----------------
__global__ void select_kernel()
{
    __shared__ int ssc[NCv];
    __shared__ int red[1024];
    const int ch = blockIdx.x;
    const int* score = g_score + ch * NCv;
    int* sids = g_sids + ch * SSv;
    int tid = threadIdx.x;
    for (int i = tid; i < NCv; i += 1024) ssc[i] = score[i];
    __syncthreads();

    int lo = 0, hi = LTv * TPPv + 1;
    while (lo + 1 < hi) {
        int mid = (lo + hi) >> 1;
        int c = 0;
        for (int i = tid; i < NCv; i += 1024) c += (ssc[i] >= mid);
        red[tid] = c; __syncthreads();
        for (int st = 512; st > 0; st >>= 1) { if (tid < st) red[tid] += red[tid + st]; __syncthreads(); }
        int tot = red[0]; __syncthreads();
        if (tot >= SSv) lo = mid; else hi = mid;
    }
    int tau = lo;
    int c = 0;
    for (int i = tid; i < NCv; i += 1024) c += (ssc[i] > tau);
    red[tid] = c; __syncthreads();
    for (int st = 512; st > 0; st >>= 1) { if (tid < st) red[tid] += red[tid + st]; __syncthreads(); }
    int m = red[0];
    int need = SSv - m;
    __syncthreads();

    int base = tid * 4;
    int gtp[4], eqp[4];
    int lgt = 0, leq = 0;
    #pragma unroll
    for (int j = 0; j < 4; j++) {
        int sc = ssc[base + j];
        gtp[j] = lgt; eqp[j] = leq;
        lgt += (sc > tau); leq += (sc == tau);
    }
    red[tid] = (lgt << 16) | leq; __syncthreads();
    for (int off = 1; off < 1024; off <<= 1) {
        int vv = (tid >= off) ? red[tid - off] : 0;
        __syncthreads();
        red[tid] += vv;
        __syncthreads();
    }
    int excl = (tid == 0) ? 0 : red[tid - 1];
    int egt = excl >> 16, eeq = excl & 0xffff;
    #pragma unroll
    for (int j = 0; j < 4; j++) {
        int sc = ssc[base + j];
        if (sc > tau)                                sids[egt + gtp[j]] = base + j;
        else if (sc == tau && (eeq + eqp[j]) < need) sids[m + eeq + eqp[j]] = base + j;
    }
}

// ---------------- gathers (both chunks) ----------------
__global__ void gather_kernel(const float* __restrict__ W1, const float* __restrict__ b1)
{
    int idx = blockIdx.x * 256 + threadIdx.x;   // 2*SS*D
    if (idx >= 2 * SSv * Dv) return;
    int ch = idx >> 20;
    int s = (idx >> 10) & 1023, dcol = idx & 1023;
    int row = g_sids[ch * SSv + s];
    g_w1s[idx] = W1[(size_t)row * Dv + dcol];
    if (dcol == 0) g_b1s[ch * SSv + s] = b1[row];
}
__global__ void gatherT_kernel(const float* __restrict__ W2)
{
    __shared__ float tile[32][33];
    int ch = blockIdx.x / (SSv / 32);
    int s0 = (blockIdx.x % (SSv / 32)) * 32, d0 = blockIdx.y * 32;
    int tx = threadIdx.x & 31, ty8 = threadIdx.x >> 5;
    for (int r = ty8; r < 32; r += 8) {
        int row = g_sids[ch * SSv + s0 + r];
        tile[r][tx] = W2[(size_t)row * Dv + d0 + tx];
    }
    __syncthreads();
    float* dst = g_w2sT + (size_t)ch * Dv * SSv;
    for (int r = ty8; r < 32; r += 8)
        dst[(size_t)(d0 + r) * SSv + s0 + tx] = tile[tx][r];
}
__global__ void tanhpns_kernel()
{
    int idx = blockIdx.x * 256 + threadIdx.x;   // 2*SS*LK
    if (idx >= 2 * SSv * LKv) return;
    int ch = idx >> 17;
    int s = (idx >> 7) & 1023, lk = idx & 127;
    int row = g_sids[ch * SSv + s];
    g_tanhpns[idx] = tanhf(g_projn[(size_t)lk * NCv + row]);
}

// ---------------- triplet loss (warp per token, all tokens) ----------------
__global__ void __launch_bounds__(256)
triplet2()
{
    __shared__ float vals[8][1024];
    int w = threadIdx.x >> 5, lane = threadIdx.x & 31;
    int t = blockIdx.x * 8 + w;
    int ch = t >> 10;
    const float* lrow = g_logits + (size_t)t * SSv;
    const float* tpns = g_tanhpns + (size_t)ch * SSv * LKv;

    float apos = 0.f, aneg = 0.f;
    for (int phase = 0; phase < 2; phase++) {
        for (int i = lane; i < 256; i += 32)
            ((float4*)vals[w])[i] = ((const float4*)lrow)[i];
        __syncwarp();
        float sv[4] = {0.f, 0.f, 0.f, 0.f};
        for (int it = 0; it < PPv; it++) {
            float bv = (phase == 0) ? -1e30f : 1e30f;
            int bi = 1 << 30;
            #pragma unroll
            for (int qd = 0; qd < 32; qd++) {
                int i = lane + (qd << 5);
                float x = vals[w][i];
                bool better = (phase == 0) ? (x > bv) : (x < bv);
                if (better) { bv = x; bi = i; }
            }
            #pragma unroll
            for (int off = 16; off > 0; off >>= 1) {
                float ov = __shfl_xor_sync(0xffffffffu, bv, off);
                int   oi = __shfl_xor_sync(0xffffffffu, bi, off);
                bool take = (phase == 0)
                    ? (ov > bv || (ov == bv && oi < bi))
                    : (ov < bv || (ov == bv && oi < bi));
                if (take) { bv = ov; bi = oi; }
            }
            #pragma unroll
            for (int c2 = 0; c2 < 4; c2++)
                sv[c2] += tpns[(size_t)bi * LKv + lane + 32 * c2];
            if (lane == 0) vals[w][bi] = (phase == 0) ? -1e30f : 1e30f;
            __syncwarp();
        }
        float a = 0.f;
        #pragma unroll
        for (int c2 = 0; c2 < 4; c2++)
            a += sv[c2] * g_tanhpt[(size_t)t * LKv + lane + 32 * c2];
        #pragma unroll
        for (int off = 16; off > 0; off >>= 1)
            a += __shfl_xor_sync(0xffffffffu, a, off);
        a *= 1.0f / (128.0f * 64.0f);
        if (phase == 0) apos = a; else aneg = a;
    }
    if (lane == 0) g_trip[t] = fmaxf(aneg - apos + 0.5f, 0.f);
}

__global__ void trip_reduce(float* __restrict__ outp)
{
    __shared__ float red[1024];
    int tid = threadIdx.x;
    red[tid] = g_trip[tid] + g_trip[tid + 1024];
    __syncthreads();
    for (int st = 512; st > 0; st >>= 1) { if (tid < st) red[tid] += red[tid + st]; __syncthreads(); }
    if (tid == 0) *outp = red[0] * (1.0f / 2048.0f);
}

// ---------------- host ----------------
extern "C" void kernel_launch(void* const* d_in, const int* in_sizes, int n_in,
                              void* d_out, int out_size)
{
    const float* hidden = (const float*)d_in[0];
    const float* amask  = (const float*)d_in[1];
    const float* ln1_g  = (const float*)d_in[2];
    const float* ln1_b  = (const float*)d_in[3];
    const float* Wq     = (const float*)d_in[4];
    const float* bq     = (const float*)d_in[5];
    const float* Wk     = (const float*)d_in[6];
    const float* bk     = (const float*)d_in[7];
    const float* Wv     = (const float*)d_in[8];
    const float* bv     = (const float*)d_in[9];
    const float* Wo     = (const float*)d_in[10];
    const float* bo     = (const float*)d_in[11];
    const float* ln2_g  = (const float*)d_in[12];
    const float* ln2_b  = (const float*)d_in[13];
    const float* W1     = (const float*)d_in[14];
    const float* b1     = (const float*)d_in[15];
    const float* Whash  = (const float*)d_in[16];
    const float* W2     = (const float*)d_in[17];
    const float* b2     = (const float*)d_in[18];
    float* out = (float*)d_out;

    float *xln, *ctx, *attn, *normed, *projn, *projt;
    float *w1s, *w2sT, *b1s, *logits, *acts;
    unsigned *qh, *ql, *kh, *kl, *vh, *vl;
    int* histp;
    cudaGetSymbolAddress((void**)&xln,    g_xln);
    cudaGetSymbolAddress((void**)&qh,     g_qh);
    cudaGetSymbolAddress((void**)&ql,     g_ql);
    cudaGetSymbolAddress((void**)&kh,     g_kh);
    cudaGetSymbolAddress((void**)&kl,     g_kl);
    cudaGetSymbolAddress((void**)&vh,     g_vh);
    cudaGetSymbolAddress((void**)&vl,     g_vl);
    cudaGetSymbolAddress((void**)&ctx,    g_ctx);
    cudaGetSymbolAddress((void**)&attn,   g_attn);
    cudaGetSymbolAddress((void**)&normed, g_normed);
    cudaGetSymbolAddress((void**)&projn,  g_projn);
    cudaGetSymbolAddress((void**)&projt,  g_projt);
    cudaGetSymbolAddress((void**)&w1s,    g_w1s);
    cudaGetSymbolAddress((void**)&w2sT,   g_w2sT);
    cudaGetSymbolAddress((void**)&b1s,    g_b1s);
    cudaGetSymbolAddress((void**)&logits, g_logits);
    cudaGetSymbolAddress((void**)&acts,   g_acts);
    cudaGetSymbolAddress((void**)&histp,  g_hist);

    const int SM3  = (128 + 128) * 36 * 4 * 2;   // 73728
    const int SM1  = (64 + 128) * 36 * 4;        // 27648
    const int SMAT = (4*64*LDQ + 2*64*LDVt) * 4 + 64*4;
    cudaFuncSetAttribute((const void*)mma_nt<3,2,true,false,128,128>,
                         cudaFuncAttributeMaxDynamicSharedMemorySize, SM3);
    cudaFuncSetAttribute((const void*)mma_nt<3,0,true,true,128,128>,
                         cudaFuncAttributeMaxDynamicSharedMemorySize, SM3);
    cudaFuncSetAttribute((const void*)mma_nt<1,1,true,false,64,128>,
                         cudaFuncAttributeMaxDynamicSharedMemorySize, SM1);
    cudaFuncSetAttribute((const void*)mma_nt<1,0,true,true,64,128>,
                         cudaFuncAttributeMaxDynamicSharedMemorySize, SM1);
    cudaFuncSetAttribute((const void*)attn4,
                         cudaFuncAttributeMaxDynamicSharedMemorySize, SMAT);

    // ---- attention path ----
    ln_kernel<<<SQv, 256>>>(hidden, ln1_g, ln1_b, xln);
    msk_kernel<<<SQv/256, 256>>>(amask);
    dim3 gA(Dv/128, SQv/128);
    mma_nt<3,2,true,false,128,128><<<gA, 256, SM3>>>(xln, Wq, bq, nullptr, (float*)qh, (float*)ql, SQv, Dv, Dv);
    mma_nt<3,2,true,false,128,128><<<gA, 256, SM3>>>(xln, Wk, bk, nullptr, (float*)kh, (float*)kl, SQv, Dv, Dv);
    mma_nt<3,2,true,false,128,128><<<gA, 256, SM3>>>(xln, Wv, bv, nullptr, (float*)vh, (float*)vl, SQv, Dv, Dv);
    attn4<<<dim3(SQv/64, Hv), 128, SMAT>>>(qh, ql, kh, kl, vh, vl, ctx);
    mma_nt<3,0,true,true,128,128><<<gA, 256, SM3>>>(ctx, Wo, bo, hidden, attn, nullptr, SQv, Dv, Dv);

    // ---- FFN prep ----
    ln_kernel<<<SQv, 256>>>(attn, ln2_g, ln2_b, normed);
    gemm_nt<false><<<dim3(NCv/64, LKv/64), 256>>>(Whash, W1, nullptr, projn, LKv, NCv, Dv);
    coden_kernel<<<(LTv * NCv) / 256, 256>>>();

    // ---- LSH FFN, fused across chunks (non-GEMM parts) ----
    gemm_nt<false><<<dim3(NTOK/64, LKv/64), 256>>>(Whash, normed, nullptr, projt, LKv, NTOK, Dv);
    cudaMemsetAsync(histp, 0, 2 * LTv * NBv * sizeof(int), 0);
    codet_hist_kernel<<<(LTv * NTOK) / 256, 256>>>();
    tanhpt_kernel<<<(NTOK * LKv) / 256, 256>>>();
    score_kernel<<<(2 * NCv) / 256, 256>>>();
    select_kernel<<<2, 1024>>>();
    gather_kernel<<<(2 * SSv * Dv) / 256, 256>>>(W1, b1);
    gatherT_kernel<<<dim3(2 * SSv / 32, Dv / 32), 256>>>(W2);
    tanhpns_kernel<<<(2 * SSv * LKv) / 256, 256>>>();

    // ---- per-chunk GEMMs (round-4 launch style) ----
    dim3 gB(SSv/128, TPPv/64);
    for (int c = 0; c < 2; c++) {
        const float* hch = normed + (size_t)c * TPPv * Dv;
        const float* ach = attn   + (size_t)c * TPPv * Dv;
        float*       och = out    + (size_t)c * TPPv * Dv;
        float*       lch = logits + (size_t)c * TPPv * SSv;
        float*       gch = acts   + (size_t)c * TPPv * SSv;

        mma_nt<1,1,true,false,64,128><<<gB, 256, SM1>>>(hch, w1s + (size_t)c * SSv * Dv,
                                                        b1s + c * SSv, nullptr,
                                                        lch, gch, TPPv, SSv, Dv);
        mma_nt<1,0,true,true,64,128><<<dim3(Dv/128, TPPv/64), 256, SM1>>>(
            gch, w2sT + (size_t)c * Dv * SSv, b2, ach, och, nullptr, TPPv, Dv, SSv);
    }
    triplet2<<<NTOK/8, 256>>>();

    // ---- scalar output ----
    trip_reduce<<<1, 1024>>>(out + (size_t)SQv * Dv);
}